// round 9
// baseline (speedup 1.0000x reference)
#include <cuda_runtime.h>

// AdaptiveSudokuLoss: ce + 0.5 * constraint + 0.1 * entropy, fused single kernel.
// outputs: (B, 81, 9) fp32, targets: (B, 81) int32, out: scalar fp32.
//
// R9: coalesced copy directly into padded smem layout (kills the ~205 cyc/batch
// scattered-LDG term that dominated R7), softmax from smem with in-place prob
// writeback (no extra barrier: each cell's 9 words owned by one thread), and
// R7's vectorized homogeneous-warp phase 2. 3 syncs per 7-batch tile.

#define THREADS 192
#define GTILE 7
#define ROWSTRIDE 84                  // words per sudoku row (81 + 3 pad)
#define BATCHSTRIDE (9 * ROWSTRIDE)   // 756 words per batch element
#define GRID 888                      // 6 blocks/SM * 148 SMs

__device__ float g_ce[GRID];
__device__ float g_cons[GRID];
__device__ float g_conf[GRID];
__device__ unsigned int g_count = 0;

__global__ __launch_bounds__(THREADS)
void sudoku_loss_fused(const float* __restrict__ outp,
                       const int* __restrict__ tgt,
                       int Bn,
                       float* __restrict__ d_out)
{
    __shared__ __align__(16) float sp[GTILE * BATCHSTRIDE];
    __shared__ float wr[6][3];
    __shared__ bool is_last;

    const int tid = threadIdx.x;
    const int ntiles = (Bn + GTILE - 1) / GTILE;

    float ce_acc = 0.f, cons_acc = 0.f, conf_acc = 0.f;

    for (int t = blockIdx.x; t < ntiles; t += gridDim.x) {
        const int b0 = t * GTILE;
        const int nvalid = (Bn - b0 < GTILE) ? (Bn - b0) : GTILE;
        const int ncells = nvalid * 81;
        const int nwords = nvalid * 729;

        // ---- phase 0: coalesced copy gmem -> padded smem --------------------
        {
            const float* __restrict__ src = outp + (size_t)b0 * 729;
            for (int i = tid; i < nwords; i += THREADS) {
                const int row = i / 81;            // global row within tile
                const int col = i - row * 81;
                sp[row * ROWSTRIDE + col] = src[i];
            }
        }
        __syncthreads();

        // ---- phase 1: per-cell softmax from smem; probs back in place -------
        for (int cell = tid; cell < ncells; cell += THREADS) {
            const int bl = cell / 81;
            const int q  = cell - bl * 81;          // r*9 + c
            const int r  = q / 9;
            const int c  = q - r * 9;
            float* __restrict__ x = sp + bl * BATCHSTRIDE + r * ROWSTRIDE + c * 9;

            float v[9];
            #pragma unroll
            for (int j = 0; j < 9; j++) v[j] = x[j];

            float m = v[0];
            #pragma unroll
            for (int j = 1; j < 9; j++) m = fmaxf(m, v[j]);

            float e[9];
            float s = 0.f;
            #pragma unroll
            for (int j = 0; j < 9; j++) { e[j] = __expf(v[j] - m); s += e[j]; }

            const float inv = __frcp_rn(s);
            float sx = 0.f;
            #pragma unroll
            for (int j = 0; j < 9; j++) {
                const float p = e[j] * inv;
                x[j] = p;                           // in place: sole owner
                sx = fmaf(p, v[j], sx);
            }
            const float lse = m + __logf(s);

            const int tv = tgt[(size_t)(b0 + bl) * 81 + q];
            float xt = 0.f;
            #pragma unroll
            for (int j = 0; j < 9; j++) xt += (j == tv) ? v[j] : 0.f;

            ce_acc   += lse - xt;    // -logp[target]
            conf_acc += lse - sx;    // entropy
        }
        __syncthreads();

        // ---- phase 2: 27 units per batch, homogeneous warps ----------------
        const int wtype = tid >> 6;          // 0=rows, 1=cols, 2=boxes
        const int u     = tid & 63;          // unit id within type, 63 valid
        const int bl    = u / 9;
        const int idx   = u - bl * 9;

        if (u < 63 && bl < nvalid) {
            float s[9];
            #pragma unroll
            for (int d = 0; d < 9; d++) s[d] = -1.f;

            const float* __restrict__ base = sp + bl * BATCHSTRIDE;

            if (wtype == 0) {
                // row idx: 81 contiguous floats -> 20 float4 + 1 scalar
                const float4* __restrict__ rp =
                    (const float4*)(base + idx * ROWSTRIDE);
                #pragma unroll
                for (int k = 0; k < 20; k++) {
                    const float4 v = rp[k];
                    s[(4 * k + 0) % 9] += v.x;
                    s[(4 * k + 1) % 9] += v.y;
                    s[(4 * k + 2) % 9] += v.z;
                    s[(4 * k + 3) % 9] += v.w;
                }
                s[8] += base[idx * ROWSTRIDE + 80];
            } else if (wtype == 1) {
                // col idx: 9 cells, 9 contiguous digits each
                #pragma unroll
                for (int r = 0; r < 9; r++) {
                    const float* __restrict__ cp = base + r * ROWSTRIDE + idx * 9;
                    #pragma unroll
                    for (int d = 0; d < 9; d++) s[d] += cp[d];
                }
            } else {
                // box idx: 3 row-fragments of 27 contiguous floats
                const int br = idx / 3, bc = idx - br * 3;
                #pragma unroll
                for (int i = 0; i < 3; i++) {
                    const float* __restrict__ bp =
                        base + (3 * br + i) * ROWSTRIDE + 27 * bc;
                    #pragma unroll
                    for (int k = 0; k < 27; k++) s[k % 9] += bp[k];
                }
            }

            #pragma unroll
            for (int d = 0; d < 9; d++) cons_acc = fmaf(s[d], s[d], cons_acc);
        }
        __syncthreads();   // smem reused next tile
    }

    // ---- block reduction: 3 scalars over 6 warps ----------------------------
    #pragma unroll
    for (int o = 16; o > 0; o >>= 1) {
        ce_acc   += __shfl_down_sync(0xffffffffu, ce_acc,   o);
        cons_acc += __shfl_down_sync(0xffffffffu, cons_acc, o);
        conf_acc += __shfl_down_sync(0xffffffffu, conf_acc, o);
    }
    const int wid = tid >> 5, lid = tid & 31;
    if (lid == 0) { wr[wid][0] = ce_acc; wr[wid][1] = cons_acc; wr[wid][2] = conf_acc; }
    __syncthreads();

    if (tid == 0) {
        float a = 0.f, b = 0.f, c = 0.f;
        #pragma unroll
        for (int w = 0; w < 6; w++) { a += wr[w][0]; b += wr[w][1]; c += wr[w][2]; }
        g_ce[blockIdx.x]   = a;
        g_cons[blockIdx.x] = b;
        g_conf[blockIdx.x] = c;
        __threadfence();
        const unsigned ticket = atomicAdd(&g_count, 1u);
        is_last = (ticket == gridDim.x - 1);
        if (is_last) g_count = 0;           // reset for graph replay
    }
    __syncthreads();

    // ---- last block: deterministic final reduce + combine -------------------
    if (is_last) {
        float a = 0.f, b = 0.f, c = 0.f;
        for (int i = tid; i < (int)gridDim.x; i += THREADS) {
            a += g_ce[i]; b += g_cons[i]; c += g_conf[i];
        }
        #pragma unroll
        for (int o = 16; o > 0; o >>= 1) {
            a += __shfl_down_sync(0xffffffffu, a, o);
            b += __shfl_down_sync(0xffffffffu, b, o);
            c += __shfl_down_sync(0xffffffffu, c, o);
        }
        if (lid == 0) { wr[wid][0] = a; wr[wid][1] = b; wr[wid][2] = c; }
        __syncthreads();
        if (tid == 0) {
            float fa = 0.f, fb = 0.f, fc = 0.f;
            #pragma unroll
            for (int w = 0; w < 6; w++) { fa += wr[w][0]; fb += wr[w][1]; fc += wr[w][2]; }
            const float Ncells = (float)Bn * 81.0f;
            d_out[0] = fa / Ncells
                     + 0.5f * fb / ((float)Bn * 9.0f * 27.0f)
                     + 0.1f * fc / (Ncells + 1e-8f);
        }
    }
}

extern "C" void kernel_launch(void* const* d_in, const int* in_sizes, int n_in,
                              void* d_out, int out_size)
{
    const float* outp = (const float*)d_in[0];   // (B, 81, 9) fp32
    const int*   tgt  = (const int*)d_in[1];     // (B, 81) int32
    float*       out  = (float*)d_out;

    const int Bn = in_sizes[0] / (81 * 9);
    sudoku_loss_fused<<<GRID, THREADS>>>(outp, tgt, Bn, out);
}